// round 5
// baseline (speedup 1.0000x reference)
#include <cuda_runtime.h>
#include <math.h>

// ---------------------------------------------------------------------------
// Problem constants
// ---------------------------------------------------------------------------
#define NNODES 50000
#define NEDGES 800000
#define HID    256        // hidden dim (w1 rows, AGNN feature dim)
#define KIN    512        // input dim
#define NOUT   64         // output classes

// ---------------------------------------------------------------------------
// Device scratch (no allocations allowed)
// ---------------------------------------------------------------------------
__device__ float g_h[(size_t)NNODES * HID];   // relu(x@w1^T+b1)
__device__ float g_inv[NNODES];               // 1 / max(||f||, eps)
__device__ int   g_cnt[NNODES];
__device__ int   g_rowptr[NNODES + 1];
__device__ int   g_cursor[NNODES];
__device__ int   g_col[NEDGES];
__device__ int   g_is64;                      // edge_index dtype flag

// ---------------------------------------------------------------------------
// Helpers
// ---------------------------------------------------------------------------
__device__ __forceinline__ float warp_sum(float v) {
#pragma unroll
    for (int o = 16; o > 0; o >>= 1)
        v += __shfl_xor_sync(0xFFFFFFFFu, v, o);
    return v;
}
__device__ __forceinline__ float warp_max(float v) {
#pragma unroll
    for (int o = 16; o > 0; o >>= 1)
        v = fmaxf(v, __shfl_xor_sync(0xFFFFFFFFu, v, o));
    return v;
}
__device__ __forceinline__ float dot8(float4 a0, float4 a1, float4 b0, float4 b1) {
    return a0.x * b0.x + a0.y * b0.y + a0.z * b0.z + a0.w * b0.w +
           a1.x * b1.x + a1.y * b1.y + a1.z * b1.z + a1.w * b1.w;
}
__device__ __forceinline__ int clampN(int v, int n) {
    return v < 0 ? 0 : (v >= n ? n - 1 : v);
}
// Fetch src/dst node id for edge i, robust to int32 vs int64 edge_index.
// ei: raw 32-bit view of edge_index [2, E]. half = 0 (src) or 1 (dst).
__device__ __forceinline__ int edge_id(const int* __restrict__ ei,
                                       int E, int half, int i, int is64) {
    if (is64) return ei[((size_t)half * E + i) * 2];     // low word of int64
    return ei[(size_t)half * E + i];
}

// ---------------------------------------------------------------------------
// dtype detection: int64 edge_index (values < 2^31, >=0) has all-zero odd
// 32-bit words; random int32 node ids cannot. One thread, 1024 samples.
// ---------------------------------------------------------------------------
__global__ void detect_dtype_kernel(const int* __restrict__ ei, int e) {
    int nz = 0;
    int lim = e < 1024 ? e : 1024;
    for (int i = 0; i < lim; i++) nz |= ei[2 * i + 1];
    g_is64 = (nz == 0) ? 1 : 0;
}

// ---------------------------------------------------------------------------
// GEMM1: g_h[M,256] = relu(A[M,512] @ B[256,512]^T + bias), fp32 SIMT
// 128x128 tile, 8x8 per thread, K-step 8.
// ---------------------------------------------------------------------------
__global__ __launch_bounds__(256) void gemm1_relu_kernel(
    const float* __restrict__ A,     // [M, K]
    const float* __restrict__ B,     // [256, K]  (w1)
    const float* __restrict__ bias,  // [256]
    int M, int K)
{
    __shared__ float As[8][128];
    __shared__ float Bs[8][128];

    const int tid = threadIdx.x;
    const int bm = blockIdx.y * 128;
    const int bn = blockIdx.x * 128;

    const int tr = (tid / 16) * 8;   // row base within tile
    const int tc = (tid % 16) * 8;   // col base within tile

    const int lr = tid >> 1;         // 0..127 (tile row for loads)
    const int lk = (tid & 1) * 4;    // 0 or 4

    float acc[8][8];
#pragma unroll
    for (int i = 0; i < 8; i++)
#pragma unroll
        for (int j = 0; j < 8; j++) acc[i][j] = 0.0f;

    for (int k0 = 0; k0 < K; k0 += 8) {
        float4 av = make_float4(0.f, 0.f, 0.f, 0.f);
        if (bm + lr < M)
            av = *(const float4*)&A[(size_t)(bm + lr) * K + k0 + lk];
        As[lk + 0][lr] = av.x; As[lk + 1][lr] = av.y;
        As[lk + 2][lr] = av.z; As[lk + 3][lr] = av.w;

        float4 bv = *(const float4*)&B[(size_t)(bn + lr) * K + k0 + lk];
        Bs[lk + 0][lr] = bv.x; Bs[lk + 1][lr] = bv.y;
        Bs[lk + 2][lr] = bv.z; Bs[lk + 3][lr] = bv.w;

        __syncthreads();

#pragma unroll
        for (int kk = 0; kk < 8; kk++) {
            float ra[8], rb[8];
#pragma unroll
            for (int i = 0; i < 8; i++) ra[i] = As[kk][tr + i];
#pragma unroll
            for (int j = 0; j < 8; j++) rb[j] = Bs[kk][tc + j];
#pragma unroll
            for (int i = 0; i < 8; i++)
#pragma unroll
                for (int j = 0; j < 8; j++)
                    acc[i][j] += ra[i] * rb[j];
        }
        __syncthreads();
    }

#pragma unroll
    for (int i = 0; i < 8; i++) {
        const int row = bm + tr + i;
        if (row >= M) continue;
#pragma unroll
        for (int j = 0; j < 8; j++) {
            const int col = bn + tc + j;
            g_h[(size_t)row * HID + col] = fmaxf(acc[i][j] + bias[col], 0.0f);
        }
    }
}

// ---------------------------------------------------------------------------
// Per-node 1/max(||f||, eps)  — one warp per node.
// f == nullptr -> read from g_h.
// ---------------------------------------------------------------------------
__global__ void inv_norm_kernel(const float* __restrict__ f, int n)
{
    const int warp = (blockIdx.x * blockDim.x + threadIdx.x) >> 5;
    if (warp >= n) return;
    const int lane = threadIdx.x & 31;
    const float4* F = (const float4*)(f ? f : (const float*)g_h);
    const size_t base = (size_t)warp * (HID / 4);
    float4 a = F[base + lane], b = F[base + 32 + lane];
    float s = dot8(a, b, a, b);
    s = warp_sum(s);
    if (lane == 0)
        g_inv[warp] = 1.0f / fmaxf(sqrtf(s), 1e-12f);
}

// ---------------------------------------------------------------------------
// CSR build (dtype-robust, clamped indexing)
// ---------------------------------------------------------------------------
__global__ void zero_cnt_kernel(int n) {
    int i = blockIdx.x * blockDim.x + threadIdx.x;
    if (i < n) g_cnt[i] = 0;
}

__global__ void count_kernel(const int* __restrict__ ei, int e, int n) {
    int i = blockIdx.x * blockDim.x + threadIdx.x;
    if (i < e) {
        int d = clampN(edge_id(ei, e, 1, i, g_is64), n);
        atomicAdd(&g_cnt[d], 1);
    }
}

__global__ __launch_bounds__(1024) void scan_kernel(int n) {
    __shared__ int sums[1024];
    const int tid = threadIdx.x;
    const int CH = (n + 1023) / 1024;
    const int start = tid * CH;

    int s = 0;
    for (int i = 0; i < CH; i++) {
        int idx = start + i;
        if (idx < n) s += g_cnt[idx];
    }
    sums[tid] = s;
    __syncthreads();
#pragma unroll
    for (int off = 1; off < 1024; off <<= 1) {
        int v = (tid >= off) ? sums[tid - off] : 0;
        __syncthreads();
        sums[tid] += v;
        __syncthreads();
    }
    int run = (tid == 0) ? 0 : sums[tid - 1];
    for (int i = 0; i < CH; i++) {
        int idx = start + i;
        if (idx < n) {
            g_rowptr[idx] = run;
            g_cursor[idx] = run;
            run += g_cnt[idx];
        }
    }
    if (tid == 1023) g_rowptr[n] = sums[1023];
}

__global__ void scatter_kernel(const int* __restrict__ ei, int e, int n) {
    int i = blockIdx.x * blockDim.x + threadIdx.x;
    if (i < e) {
        const int is64 = g_is64;
        int d = clampN(edge_id(ei, e, 1, i, is64), n);
        int sidx = clampN(edge_id(ei, e, 0, i, is64), n);
        int p = atomicAdd(&g_cursor[d], 1);
        if (p < NEDGES) g_col[p] = sidx;
    }
}

// ---------------------------------------------------------------------------
// AGNN propagation — one warp per destination node, online softmax,
// 2-way unrolled edge loop for load/shuffle latency overlap.
// score(j->i) = beta * <f_i, f_j> * inv_i * inv_j ; out_i = sum alpha_ij f_j
// Self-loop folded in as the initial state.
// f == nullptr -> read from g_h.
// ---------------------------------------------------------------------------
__global__ __launch_bounds__(256) void agnn_kernel(
    const float* __restrict__ f,
    const float* __restrict__ beta_ptr,  // may be null -> beta = 1
    float* __restrict__ out, int n)
{
    const int node = (blockIdx.x * blockDim.x + threadIdx.x) >> 5;
    if (node >= n) return;
    const int lane = threadIdx.x & 31;

    const float beta = beta_ptr ? __ldg(beta_ptr) : 1.0f;

    const float4* F = (const float4*)(f ? f : (const float*)g_h);
    const size_t base = (size_t)node * (HID / 4);

    float4 fi0 = F[base + lane];
    float4 fi1 = F[base + 32 + lane];
    const float invi = g_inv[node];

    // self loop: score = beta * ||f_i||^2 * inv_i^2
    float d = dot8(fi0, fi1, fi0, fi1);
    d = warp_sum(d);
    float m = beta * d * invi * invi;
    float s = 1.0f;
    float4 acc0 = fi0;
    float4 acc1 = fi1;

    const int beg = g_rowptr[node];
    const int end = g_rowptr[node + 1];
    int e = beg;

    // main loop: 2 edges per iteration (independent loads + reductions)
    for (; e + 1 < end; e += 2) {
        const int j0 = g_col[e];
        const int j1 = g_col[e + 1];
        const size_t jb0 = (size_t)j0 * (HID / 4);
        const size_t jb1 = (size_t)j1 * (HID / 4);
        float4 fa0 = F[jb0 + lane];
        float4 fa1 = F[jb0 + 32 + lane];
        float4 fb0 = F[jb1 + lane];
        float4 fb1 = F[jb1 + 32 + lane];

        float pa = dot8(fi0, fi1, fa0, fa1);
        float pb = dot8(fi0, fi1, fb0, fb1);
#pragma unroll
        for (int o = 16; o > 0; o >>= 1) {
            pa += __shfl_xor_sync(0xFFFFFFFFu, pa, o);
            pb += __shfl_xor_sync(0xFFFFFFFFu, pb, o);
        }
        const float sc_a = beta * pa * invi * g_inv[j0];
        const float sc_b = beta * pb * invi * g_inv[j1];

        // sequential online-softmax updates (order e, then e+1)
        {
            const float mn = fmaxf(m, sc_a);
            const float cs = __expf(m - mn);
            const float w  = __expf(sc_a - mn);
            s = s * cs + w;
            acc0.x = acc0.x * cs + w * fa0.x;  acc0.y = acc0.y * cs + w * fa0.y;
            acc0.z = acc0.z * cs + w * fa0.z;  acc0.w = acc0.w * cs + w * fa0.w;
            acc1.x = acc1.x * cs + w * fa1.x;  acc1.y = acc1.y * cs + w * fa1.y;
            acc1.z = acc1.z * cs + w * fa1.z;  acc1.w = acc1.w * cs + w * fa1.w;
            m = mn;
        }
        {
            const float mn = fmaxf(m, sc_b);
            const float cs = __expf(m - mn);
            const float w  = __expf(sc_b - mn);
            s = s * cs + w;
            acc0.x = acc0.x * cs + w * fb0.x;  acc0.y = acc0.y * cs + w * fb0.y;
            acc0.z = acc0.z * cs + w * fb0.z;  acc0.w = acc0.w * cs + w * fb0.w;
            acc1.x = acc1.x * cs + w * fb1.x;  acc1.y = acc1.y * cs + w * fb1.y;
            acc1.z = acc1.z * cs + w * fb1.z;  acc1.w = acc1.w * cs + w * fb1.w;
            m = mn;
        }
    }

    // remainder
    for (; e < end; e++) {
        const int j = g_col[e];
        const size_t jb = (size_t)j * (HID / 4);
        float4 fj0 = F[jb + lane];
        float4 fj1 = F[jb + 32 + lane];

        float pd = dot8(fi0, fi1, fj0, fj1);
        pd = warp_sum(pd);
        const float score = beta * pd * invi * g_inv[j];

        const float mn = fmaxf(m, score);
        const float cs = __expf(m - mn);
        const float w  = __expf(score - mn);
        s = s * cs + w;
        acc0.x = acc0.x * cs + w * fj0.x;  acc0.y = acc0.y * cs + w * fj0.y;
        acc0.z = acc0.z * cs + w * fj0.z;  acc0.w = acc0.w * cs + w * fj0.w;
        acc1.x = acc1.x * cs + w * fj1.x;  acc1.y = acc1.y * cs + w * fj1.y;
        acc1.z = acc1.z * cs + w * fj1.z;  acc1.w = acc1.w * cs + w * fj1.w;
        m = mn;
    }

    const float r = 1.0f / s;
    float4 o0 = make_float4(acc0.x * r, acc0.y * r, acc0.z * r, acc0.w * r);
    float4 o1 = make_float4(acc1.x * r, acc1.y * r, acc1.z * r, acc1.w * r);
    float4* O = (float4*)out;
    O[base + lane]      = o0;
    O[base + 32 + lane] = o1;
}

// ---------------------------------------------------------------------------
// GEMM2 + log_softmax — one warp per node, lane handles classes {lane, lane+32}
// ---------------------------------------------------------------------------
__global__ __launch_bounds__(256) void gemm2_lsm_kernel(
    const float* __restrict__ z,    // [N, 256]
    const float* __restrict__ w2,   // [64, 256]
    const float* __restrict__ b2,   // [64]
    float* __restrict__ outp,       // [N, 64]
    int n)
{
    const int node = (blockIdx.x * blockDim.x + threadIdx.x) >> 5;
    if (node >= n) return;
    const int lane = threadIdx.x & 31;

    const float4* Z  = (const float4*)(z + (size_t)node * HID);
    const float4* W0 = (const float4*)(w2 + (size_t)lane * HID);
    const float4* W1 = (const float4*)(w2 + (size_t)(lane + 32) * HID);

    float v0 = 0.0f, v1 = 0.0f;
#pragma unroll 8
    for (int k = 0; k < HID / 4; k++) {
        float4 zz = Z[k];
        float4 a = W0[k];
        float4 b = W1[k];
        v0 += zz.x * a.x + zz.y * a.y + zz.z * a.z + zz.w * a.w;
        v1 += zz.x * b.x + zz.y * b.y + zz.z * b.z + zz.w * b.w;
    }
    v0 += b2[lane];
    v1 += b2[lane + 32];

    float mx = warp_max(fmaxf(v0, v1));
    float se = warp_sum(__expf(v0 - mx) + __expf(v1 - mx));
    float lse = mx + logf(se);

    outp[(size_t)node * NOUT + lane]      = v0 - lse;
    outp[(size_t)node * NOUT + lane + 32] = v1 - lse;
}

// ---------------------------------------------------------------------------
// Launch — kernel launches ONLY (graph-capture safe)
// ---------------------------------------------------------------------------
extern "C" void kernel_launch(void* const* d_in, const int* in_sizes, int n_in,
                              void* d_out, int out_size)
{
    const float* x     = (const float*)d_in[0];
    const int*   ei    = (const int*)d_in[1];     // raw 32-bit view
    const float* w1    = (const float*)d_in[2];
    const float* b1    = (const float*)d_in[3];
    const float* beta2 = (const float*)d_in[4];
    const float* w2    = (const float*)d_in[5];
    const float* b2    = (const float*)d_in[6];

    const int N = in_sizes[0] / KIN;       // 50000
    const int E = in_sizes[1] / 2;         // 800000 (element count / 2)

    float* out = (float*)d_out;
    float* z1 = out;                                   // [N, 256]
    float* z2 = out + (size_t)N * HID;                 // [N, 256]
    float* lp = out + (size_t)2 * N * HID;             // [N, 64]

    // 0) edge_index dtype detection
    detect_dtype_kernel<<<1, 1>>>(ei, E);

    // 1) GEMM1 + relu  -> g_h
    {
        dim3 grid(HID / 128, (N + 127) / 128);
        gemm1_relu_kernel<<<grid, 256>>>(x, w1, b1, N, KIN);
    }

    // 2) CSR build
    zero_cnt_kernel<<<(N + 255) / 256, 256>>>(N);
    count_kernel<<<(E + 255) / 256, 256>>>(ei, E, N);
    scan_kernel<<<1, 1024>>>(N);
    scatter_kernel<<<(E + 255) / 256, 256>>>(ei, E, N);

    const int warps_per_block = 256 / 32;
    const int gridN = (N + warps_per_block - 1) / warps_per_block;

    // 3) layer 1: norms of g_h, AGNN(beta=1) -> z1
    inv_norm_kernel<<<gridN, 256>>>(nullptr, N);
    agnn_kernel<<<gridN, 256>>>(nullptr, nullptr, z1, N);

    // 4) layer 2: norms of z1, AGNN(beta=beta2) -> z2
    inv_norm_kernel<<<gridN, 256>>>(z1, N);
    agnn_kernel<<<gridN, 256>>>(z1, beta2, z2, N);

    // 5) logits + log_softmax
    gemm2_lsm_kernel<<<gridN, 256>>>(z2, w2, b2, lp, N);
}

// round 6
// speedup vs baseline: 2.4257x; 2.4257x over previous
#include <cuda_runtime.h>
#include <cuda_bf16.h>
#include <math.h>

// ---------------------------------------------------------------------------
// Problem constants
// ---------------------------------------------------------------------------
#define NNODES 50000
#define NEDGES 800000
#define HID    256        // hidden dim
#define KIN    512        // input dim
#define NOUT   64         // output classes

// ---------------------------------------------------------------------------
// Device scratch
// ---------------------------------------------------------------------------
__device__ float g_h[(size_t)NNODES * HID];
__device__ float g_inv[NNODES];
__device__ int   g_cnt[NNODES];
__device__ int   g_rowptr[NNODES + 1];
__device__ int   g_cursor[NNODES];
__device__ int   g_col[NEDGES];
__device__ int   g_is64;

// ---------------------------------------------------------------------------
// Helpers
// ---------------------------------------------------------------------------
__device__ __forceinline__ float warp_sum(float v) {
#pragma unroll
    for (int o = 16; o > 0; o >>= 1)
        v += __shfl_xor_sync(0xFFFFFFFFu, v, o);
    return v;
}
__device__ __forceinline__ float warp_max(float v) {
#pragma unroll
    for (int o = 16; o > 0; o >>= 1)
        v = fmaxf(v, __shfl_xor_sync(0xFFFFFFFFu, v, o));
    return v;
}
__device__ __forceinline__ float dot8(float4 a0, float4 a1, float4 b0, float4 b1) {
    return a0.x * b0.x + a0.y * b0.y + a0.z * b0.z + a0.w * b0.w +
           a1.x * b1.x + a1.y * b1.y + a1.z * b1.z + a1.w * b1.w;
}
__device__ __forceinline__ int clampN(int v, int n) {
    return v < 0 ? 0 : (v >= n ? n - 1 : v);
}
__device__ __forceinline__ int edge_id(const int* __restrict__ ei,
                                       int E, int half, int i, int is64) {
    if (is64) return ei[((size_t)half * E + i) * 2];
    return ei[(size_t)half * E + i];
}
__device__ __forceinline__ void bf16_split(float v, __nv_bfloat16& hi, __nv_bfloat16& lo) {
    hi = __float2bfloat16(v);
    lo = __float2bfloat16(v - __bfloat162float(hi));
}
__device__ __forceinline__ void mma_bf16(float* d, const unsigned* a, const unsigned* b) {
    asm volatile(
        "mma.sync.aligned.m16n8k16.row.col.f32.bf16.bf16.f32 "
        "{%0,%1,%2,%3}, {%4,%5,%6,%7}, {%8,%9}, {%0,%1,%2,%3};\n"
        : "+f"(d[0]), "+f"(d[1]), "+f"(d[2]), "+f"(d[3])
        : "r"(a[0]), "r"(a[1]), "r"(a[2]), "r"(a[3]), "r"(b[0]), "r"(b[1]));
}

// ---------------------------------------------------------------------------
// dtype detection (parallel): int64 values < 2^31 have all-zero odd words.
// ---------------------------------------------------------------------------
__global__ void detect_dtype_kernel(const int* __restrict__ ei, int e) {
    int nz = 0;
    int lim = e < 4096 ? e : 4096;
    for (int i = threadIdx.x; i < lim; i += blockDim.x) nz |= ei[2 * i + 1];
    int any = __syncthreads_or(nz);
    if (threadIdx.x == 0) g_is64 = (any == 0) ? 1 : 0;
}

// ---------------------------------------------------------------------------
// GEMM1 (tensor core): g_h = relu(A[M,512] @ w1[256,512]^T + b1)
// bf16 split (hi+lo), 3-term product for ~fp32 accuracy.
// BM=128, BN=128, BK=32; 8 warps (4 m x 2 n), warp tile 32x64.
// ---------------------------------------------------------------------------
#define AS 40   // smem stride in bf16 for K=32 tiles (conflict-free frag loads)

__global__ __launch_bounds__(256) void gemm1_mma_kernel(
    const float* __restrict__ A,     // [M, 512]
    const float* __restrict__ B,     // [256, 512] (w1, row-major = col-major K x N)
    const float* __restrict__ bias,  // [256]
    int M)
{
    __shared__ __nv_bfloat16 Ah[128][AS], Al[128][AS];
    __shared__ __nv_bfloat16 Bh[128][AS], Bl[128][AS];

    const int tid = threadIdx.x;
    const int bm = blockIdx.y * 128;
    const int bn = blockIdx.x * 128;

    const int wid    = tid >> 5;
    const int lane   = tid & 31;
    const int warp_m = wid & 3;        // 0..3 -> rows warp_m*32
    const int warp_n = wid >> 2;       // 0..1 -> cols warp_n*64
    const int g      = lane >> 2;      // group id 0..7
    const int tg     = lane & 3;       // thread in group

    float acc[2][8][4];
#pragma unroll
    for (int i = 0; i < 2; i++)
#pragma unroll
        for (int j = 0; j < 8; j++)
#pragma unroll
            for (int q = 0; q < 4; q++) acc[i][j][q] = 0.0f;

    for (int kt = 0; kt < KIN / 32; kt++) {
        const int k0 = kt * 32;
        // ---- load + convert tiles: 128 rows x 32 k (fp32) each for A and B
#pragma unroll
        for (int it = 0; it < 4; it++) {
            int id  = tid + it * 256;          // 0..1023 float4 slots
            int row = id >> 3;
            int c4  = (id & 7) * 4;            // k offset
            float4 av = make_float4(0.f, 0.f, 0.f, 0.f);
            if (bm + row < M)
                av = *(const float4*)&A[(size_t)(bm + row) * KIN + k0 + c4];
            __nv_bfloat16 h0, l0, h1, l1, h2, l2, h3, l3;
            bf16_split(av.x, h0, l0); bf16_split(av.y, h1, l1);
            bf16_split(av.z, h2, l2); bf16_split(av.w, h3, l3);
            Ah[row][c4 + 0] = h0; Ah[row][c4 + 1] = h1;
            Ah[row][c4 + 2] = h2; Ah[row][c4 + 3] = h3;
            Al[row][c4 + 0] = l0; Al[row][c4 + 1] = l1;
            Al[row][c4 + 2] = l2; Al[row][c4 + 3] = l3;

            float4 bv = *(const float4*)&B[(size_t)(bn + row) * KIN + k0 + c4];
            bf16_split(bv.x, h0, l0); bf16_split(bv.y, h1, l1);
            bf16_split(bv.z, h2, l2); bf16_split(bv.w, h3, l3);
            Bh[row][c4 + 0] = h0; Bh[row][c4 + 1] = h1;
            Bh[row][c4 + 2] = h2; Bh[row][c4 + 3] = h3;
            Bl[row][c4 + 0] = l0; Bl[row][c4 + 1] = l1;
            Bl[row][c4 + 2] = l2; Bl[row][c4 + 3] = l3;
        }
        __syncthreads();

#pragma unroll
        for (int s = 0; s < 2; s++) {
            const int ks = s * 16;
            // A fragments (2 m-tiles), hi and lo
            unsigned aHi[2][4], aLo[2][4];
#pragma unroll
            for (int mi = 0; mi < 2; mi++) {
                int r0 = warp_m * 32 + mi * 16 + g;
                int kk = ks + tg * 2;
                aHi[mi][0] = *(const unsigned*)&Ah[r0][kk];
                aHi[mi][1] = *(const unsigned*)&Ah[r0 + 8][kk];
                aHi[mi][2] = *(const unsigned*)&Ah[r0][kk + 8];
                aHi[mi][3] = *(const unsigned*)&Ah[r0 + 8][kk + 8];
                aLo[mi][0] = *(const unsigned*)&Al[r0][kk];
                aLo[mi][1] = *(const unsigned*)&Al[r0 + 8][kk];
                aLo[mi][2] = *(const unsigned*)&Al[r0][kk + 8];
                aLo[mi][3] = *(const unsigned*)&Al[r0 + 8][kk + 8];
            }
            // B fragments (8 n-tiles), hi and lo
            unsigned bHi[8][2], bLo[8][2];
#pragma unroll
            for (int ni = 0; ni < 8; ni++) {
                int nrow = warp_n * 64 + ni * 8 + g;
                int kk = ks + tg * 2;
                bHi[ni][0] = *(const unsigned*)&Bh[nrow][kk];
                bHi[ni][1] = *(const unsigned*)&Bh[nrow][kk + 8];
                bLo[ni][0] = *(const unsigned*)&Bl[nrow][kk];
                bLo[ni][1] = *(const unsigned*)&Bl[nrow][kk + 8];
            }
#pragma unroll
            for (int mi = 0; mi < 2; mi++)
#pragma unroll
                for (int ni = 0; ni < 8; ni++) {
                    mma_bf16(acc[mi][ni], aHi[mi], bHi[ni]);
                    mma_bf16(acc[mi][ni], aHi[mi], bLo[ni]);
                    mma_bf16(acc[mi][ni], aLo[mi], bHi[ni]);
                }
        }
        __syncthreads();
    }

    // epilogue: bias + relu, store to g_h
#pragma unroll
    for (int mi = 0; mi < 2; mi++) {
#pragma unroll
        for (int ni = 0; ni < 8; ni++) {
            int row0 = bm + warp_m * 32 + mi * 16 + g;
            int col  = bn + warp_n * 64 + ni * 8 + tg * 2;
            float bx = bias[col], by = bias[col + 1];
            if (row0 < M) {
                float2 v = make_float2(fmaxf(acc[mi][ni][0] + bx, 0.f),
                                       fmaxf(acc[mi][ni][1] + by, 0.f));
                *(float2*)&g_h[(size_t)row0 * HID + col] = v;
            }
            if (row0 + 8 < M) {
                float2 v = make_float2(fmaxf(acc[mi][ni][2] + bx, 0.f),
                                       fmaxf(acc[mi][ni][3] + by, 0.f));
                *(float2*)&g_h[(size_t)(row0 + 8) * HID + col] = v;
            }
        }
    }
}

// ---------------------------------------------------------------------------
// Per-node 1/max(||f||, eps) — one warp per node. f==nullptr -> g_h.
// ---------------------------------------------------------------------------
__global__ void inv_norm_kernel(const float* __restrict__ f, int n)
{
    const int warp = (blockIdx.x * blockDim.x + threadIdx.x) >> 5;
    if (warp >= n) return;
    const int lane = threadIdx.x & 31;
    const float4* F = (const float4*)(f ? f : (const float*)g_h);
    const size_t base = (size_t)warp * (HID / 4);
    float4 a = F[base + lane], b = F[base + 32 + lane];
    float s = dot8(a, b, a, b);
    s = warp_sum(s);
    if (lane == 0)
        g_inv[warp] = 1.0f / fmaxf(sqrtf(s), 1e-12f);
}

// ---------------------------------------------------------------------------
// CSR build
// ---------------------------------------------------------------------------
__global__ void zero_cnt_kernel(int n) {
    int i = blockIdx.x * blockDim.x + threadIdx.x;
    if (i < n) g_cnt[i] = 0;
}

__global__ void count_kernel(const int* __restrict__ ei, int e, int n) {
    int i = blockIdx.x * blockDim.x + threadIdx.x;
    if (i < e) {
        int d = clampN(edge_id(ei, e, 1, i, g_is64), n);
        atomicAdd(&g_cnt[d], 1);
    }
}

__global__ __launch_bounds__(1024) void scan_kernel(int n) {
    __shared__ int sums[1024];
    const int tid = threadIdx.x;
    const int CH = (n + 1023) / 1024;
    const int start = tid * CH;

    int s = 0;
    for (int i = 0; i < CH; i++) {
        int idx = start + i;
        if (idx < n) s += g_cnt[idx];
    }
    sums[tid] = s;
    __syncthreads();
#pragma unroll
    for (int off = 1; off < 1024; off <<= 1) {
        int v = (tid >= off) ? sums[tid - off] : 0;
        __syncthreads();
        sums[tid] += v;
        __syncthreads();
    }
    int run = (tid == 0) ? 0 : sums[tid - 1];
    for (int i = 0; i < CH; i++) {
        int idx = start + i;
        if (idx < n) {
            g_rowptr[idx] = run;
            g_cursor[idx] = run;
            run += g_cnt[idx];
        }
    }
    if (tid == 1023) g_rowptr[n] = sums[1023];
}

__global__ void scatter_kernel(const int* __restrict__ ei, int e, int n) {
    int i = blockIdx.x * blockDim.x + threadIdx.x;
    if (i < e) {
        const int is64 = g_is64;
        int d = clampN(edge_id(ei, e, 1, i, is64), n);
        int sidx = clampN(edge_id(ei, e, 0, i, is64), n);
        int p = atomicAdd(&g_cursor[d], 1);
        if (p < NEDGES) g_col[p] = sidx;
    }
}

// ---------------------------------------------------------------------------
// AGNN propagation — warp per node, online softmax, 2-way unrolled.
// ---------------------------------------------------------------------------
__global__ __launch_bounds__(256) void agnn_kernel(
    const float* __restrict__ f,
    const float* __restrict__ beta_ptr,
    float* __restrict__ out, int n)
{
    const int node = (blockIdx.x * blockDim.x + threadIdx.x) >> 5;
    if (node >= n) return;
    const int lane = threadIdx.x & 31;

    const float beta = beta_ptr ? __ldg(beta_ptr) : 1.0f;

    const float4* F = (const float4*)(f ? f : (const float*)g_h);
    const size_t base = (size_t)node * (HID / 4);

    float4 fi0 = F[base + lane];
    float4 fi1 = F[base + 32 + lane];
    const float invi = g_inv[node];

    float d = dot8(fi0, fi1, fi0, fi1);
    d = warp_sum(d);
    float m = beta * d * invi * invi;
    float s = 1.0f;
    float4 acc0 = fi0;
    float4 acc1 = fi1;

    const int beg = g_rowptr[node];
    const int end = g_rowptr[node + 1];
    int e = beg;

    for (; e + 1 < end; e += 2) {
        const int j0 = g_col[e];
        const int j1 = g_col[e + 1];
        const size_t jb0 = (size_t)j0 * (HID / 4);
        const size_t jb1 = (size_t)j1 * (HID / 4);
        float4 fa0 = F[jb0 + lane];
        float4 fa1 = F[jb0 + 32 + lane];
        float4 fb0 = F[jb1 + lane];
        float4 fb1 = F[jb1 + 32 + lane];

        float pa = dot8(fi0, fi1, fa0, fa1);
        float pb = dot8(fi0, fi1, fb0, fb1);
#pragma unroll
        for (int o = 16; o > 0; o >>= 1) {
            pa += __shfl_xor_sync(0xFFFFFFFFu, pa, o);
            pb += __shfl_xor_sync(0xFFFFFFFFu, pb, o);
        }
        const float sc_a = beta * pa * invi * g_inv[j0];
        const float sc_b = beta * pb * invi * g_inv[j1];

        {
            const float mn = fmaxf(m, sc_a);
            const float cs = __expf(m - mn);
            const float w  = __expf(sc_a - mn);
            s = s * cs + w;
            acc0.x = acc0.x * cs + w * fa0.x;  acc0.y = acc0.y * cs + w * fa0.y;
            acc0.z = acc0.z * cs + w * fa0.z;  acc0.w = acc0.w * cs + w * fa0.w;
            acc1.x = acc1.x * cs + w * fa1.x;  acc1.y = acc1.y * cs + w * fa1.y;
            acc1.z = acc1.z * cs + w * fa1.z;  acc1.w = acc1.w * cs + w * fa1.w;
            m = mn;
        }
        {
            const float mn = fmaxf(m, sc_b);
            const float cs = __expf(m - mn);
            const float w  = __expf(sc_b - mn);
            s = s * cs + w;
            acc0.x = acc0.x * cs + w * fb0.x;  acc0.y = acc0.y * cs + w * fb0.y;
            acc0.z = acc0.z * cs + w * fb0.z;  acc0.w = acc0.w * cs + w * fb0.w;
            acc1.x = acc1.x * cs + w * fb1.x;  acc1.y = acc1.y * cs + w * fb1.y;
            acc1.z = acc1.z * cs + w * fb1.z;  acc1.w = acc1.w * cs + w * fb1.w;
            m = mn;
        }
    }

    for (; e < end; e++) {
        const int j = g_col[e];
        const size_t jb = (size_t)j * (HID / 4);
        float4 fj0 = F[jb + lane];
        float4 fj1 = F[jb + 32 + lane];

        float pd = dot8(fi0, fi1, fj0, fj1);
        pd = warp_sum(pd);
        const float score = beta * pd * invi * g_inv[j];

        const float mn = fmaxf(m, score);
        const float cs = __expf(m - mn);
        const float w  = __expf(score - mn);
        s = s * cs + w;
        acc0.x = acc0.x * cs + w * fj0.x;  acc0.y = acc0.y * cs + w * fj0.y;
        acc0.z = acc0.z * cs + w * fj0.z;  acc0.w = acc0.w * cs + w * fj0.w;
        acc1.x = acc1.x * cs + w * fj1.x;  acc1.y = acc1.y * cs + w * fj1.y;
        acc1.z = acc1.z * cs + w * fj1.z;  acc1.w = acc1.w * cs + w * fj1.w;
        m = mn;
    }

    const float r = 1.0f / s;
    float4 o0 = make_float4(acc0.x * r, acc0.y * r, acc0.z * r, acc0.w * r);
    float4 o1 = make_float4(acc1.x * r, acc1.y * r, acc1.z * r, acc1.w * r);
    float4* O = (float4*)out;
    O[base + lane]      = o0;
    O[base + 32 + lane] = o1;
}

// ---------------------------------------------------------------------------
// GEMM2 tiled: logits[128-node block][64] = z @ w2^T + b2
// 256 threads: 16x16 grid, each thread 8 nodes x 4 outs.
// ---------------------------------------------------------------------------
__global__ __launch_bounds__(256) void gemm2_tile_kernel(
    const float* __restrict__ z,    // [N, 256]
    const float* __restrict__ w2,   // [64, 256]
    const float* __restrict__ b2,   // [64]
    float* __restrict__ logits,     // [N, 64]
    int n)
{
    __shared__ float Zs[32][132];   // [k][node]
    __shared__ float Ws[32][68];    // [k][out]

    const int tid = threadIdx.x;
    const int bm = blockIdx.x * 128;
    const int tm = tid >> 4;        // 0..15 node groups of 8
    const int tn = tid & 15;        // 0..15 out groups of 4

    float acc[8][4];
#pragma unroll
    for (int i = 0; i < 8; i++)
#pragma unroll
        for (int j = 0; j < 4; j++) acc[i][j] = 0.0f;

    for (int k0 = 0; k0 < HID; k0 += 32) {
        // z block: 128 x 32 floats (transpose into Zs)
#pragma unroll
        for (int it = 0; it < 4; it++) {
            int id  = tid + it * 256;     // 0..1023
            int row = id >> 3;
            int c4  = (id & 7) * 4;
            float4 v = make_float4(0.f, 0.f, 0.f, 0.f);
            if (bm + row < n)
                v = *(const float4*)&z[(size_t)(bm + row) * HID + k0 + c4];
            Zs[c4 + 0][row] = v.x; Zs[c4 + 1][row] = v.y;
            Zs[c4 + 2][row] = v.z; Zs[c4 + 3][row] = v.w;
        }
        // w2 block: 64 x 32 floats
#pragma unroll
        for (int it = 0; it < 2; it++) {
            int id = tid + it * 256;      // 0..511
            int row = id >> 3;
            int c4  = (id & 7) * 4;
            float4 v = *(const float4*)&w2[(size_t)row * HID + k0 + c4];
            Ws[c4 + 0][row] = v.x; Ws[c4 + 1][row] = v.y;
            Ws[c4 + 2][row] = v.z; Ws[c4 + 3][row] = v.w;
        }
        __syncthreads();

#pragma unroll
        for (int kk = 0; kk < 32; kk++) {
            float4 ra0 = *(float4*)&Zs[kk][tm * 8];
            float4 ra1 = *(float4*)&Zs[kk][tm * 8 + 4];
            float4 rb  = *(float4*)&Ws[kk][tn * 4];
            float ra[8] = {ra0.x, ra0.y, ra0.z, ra0.w, ra1.x, ra1.y, ra1.z, ra1.w};
            float rbv[4] = {rb.x, rb.y, rb.z, rb.w};
#pragma unroll
            for (int i = 0; i < 8; i++)
#pragma unroll
                for (int j = 0; j < 4; j++)
                    acc[i][j] += ra[i] * rbv[j];
        }
        __syncthreads();
    }

#pragma unroll
    for (int i = 0; i < 8; i++) {
        int row = bm + tm * 8 + i;
        if (row >= n) continue;
#pragma unroll
        for (int j = 0; j < 4; j++)
            logits[(size_t)row * NOUT + tn * 4 + j] = acc[i][j] + b2[tn * 4 + j];
    }
}

// ---------------------------------------------------------------------------
// log_softmax in place over [N, 64] — one warp per node, 2 vals per lane.
// ---------------------------------------------------------------------------
__global__ void lsm_kernel(float* __restrict__ lp, int n)
{
    const int node = (blockIdx.x * blockDim.x + threadIdx.x) >> 5;
    if (node >= n) return;
    const int lane = threadIdx.x & 31;
    float2 v = *(float2*)&lp[(size_t)node * NOUT + lane * 2];
    float mx = warp_max(fmaxf(v.x, v.y));
    float se = warp_sum(__expf(v.x - mx) + __expf(v.y - mx));
    float lse = mx + logf(se);
    v.x -= lse; v.y -= lse;
    *(float2*)&lp[(size_t)node * NOUT + lane * 2] = v;
}

// ---------------------------------------------------------------------------
// Launch — gemm1 placed at launch index 3 (ncu capture slot)
// ---------------------------------------------------------------------------
extern "C" void kernel_launch(void* const* d_in, const int* in_sizes, int n_in,
                              void* d_out, int out_size)
{
    const float* x     = (const float*)d_in[0];
    const int*   ei    = (const int*)d_in[1];
    const float* w1    = (const float*)d_in[2];
    const float* b1    = (const float*)d_in[3];
    const float* beta2 = (const float*)d_in[4];
    const float* w2    = (const float*)d_in[5];
    const float* b2    = (const float*)d_in[6];

    const int N = in_sizes[0] / KIN;
    const int E = in_sizes[1] / 2;

    float* out = (float*)d_out;
    float* z1 = out;
    float* z2 = out + (size_t)N * HID;
    float* lp = out + (size_t)2 * N * HID;

    // 0-2: dtype detect + CSR count (independent of features)
    detect_dtype_kernel<<<1, 256>>>(ei, E);
    zero_cnt_kernel<<<(N + 255) / 256, 256>>>(N);
    count_kernel<<<(E + 255) / 256, 256>>>(ei, E, N);

    // 3: GEMM1 tensor-core (ncu capture slot)
    {
        dim3 grid(HID / 128, (N + 127) / 128);
        gemm1_mma_kernel<<<grid, 256>>>(x, w1, b1, N);
    }

    // 4-5: finish CSR
    scan_kernel<<<1, 1024>>>(N);
    scatter_kernel<<<(E + 255) / 256, 256>>>(ei, E, N);

    const int gridN = (N + 7) / 8;   // 8 warps per 256-thread block

    // layer 1
    inv_norm_kernel<<<gridN, 256>>>(nullptr, N);
    agnn_kernel<<<gridN, 256>>>(nullptr, nullptr, z1, N);

    // layer 2
    inv_norm_kernel<<<gridN, 256>>>(z1, N);
    agnn_kernel<<<gridN, 256>>>(z1, beta2, z2, N);

    // classifier + log_softmax
    gemm2_tile_kernel<<<(N + 127) / 128, 256>>>(z2, w2, b2, lp, N);
    lsm_kernel<<<gridN, 256>>>(lp, N);
}

// round 8
// speedup vs baseline: 2.7466x; 1.1323x over previous
#include <cuda_runtime.h>
#include <cuda_bf16.h>
#include <math.h>

// ---------------------------------------------------------------------------
// Problem constants
// ---------------------------------------------------------------------------
#define NNODES 50000
#define NEDGES 800000
#define HID    256
#define KIN    512
#define NOUT   64

// ---------------------------------------------------------------------------
// Device scratch
// ---------------------------------------------------------------------------
__device__ float g_h[(size_t)NNODES * HID];
__device__ float g_inv[NNODES];
__device__ int   g_cnt[NNODES];
__device__ int   g_rowptr[NNODES + 1];
__device__ int   g_cursor[NNODES];
__device__ int   g_col[NEDGES];
__device__ int   g_is64;

// bf16 hi/lo splits of x and w1 (pre-pass)
__device__ __nv_bfloat16 g_xhi[(size_t)NNODES * KIN];
__device__ __nv_bfloat16 g_xlo[(size_t)NNODES * KIN];
__device__ __nv_bfloat16 g_w1hi[HID * KIN];
__device__ __nv_bfloat16 g_w1lo[HID * KIN];

// ---------------------------------------------------------------------------
// Helpers
// ---------------------------------------------------------------------------
__device__ __forceinline__ float warp_sum(float v) {
#pragma unroll
    for (int o = 16; o > 0; o >>= 1)
        v += __shfl_xor_sync(0xFFFFFFFFu, v, o);
    return v;
}
__device__ __forceinline__ float warp_max(float v) {
#pragma unroll
    for (int o = 16; o > 0; o >>= 1)
        v = fmaxf(v, __shfl_xor_sync(0xFFFFFFFFu, v, o));
    return v;
}
__device__ __forceinline__ float dot8(float4 a0, float4 a1, float4 b0, float4 b1) {
    return a0.x * b0.x + a0.y * b0.y + a0.z * b0.z + a0.w * b0.w +
           a1.x * b1.x + a1.y * b1.y + a1.z * b1.z + a1.w * b1.w;
}
__device__ __forceinline__ int clampN(int v, int n) {
    return v < 0 ? 0 : (v >= n ? n - 1 : v);
}
__device__ __forceinline__ int edge_id(const int* __restrict__ ei,
                                       int E, int half, int i, int is64) {
    if (is64) return ei[((size_t)half * E + i) * 2];
    return ei[(size_t)half * E + i];
}
__device__ __forceinline__ void mma_bf16(float* d, const unsigned* a, const unsigned* b) {
    asm volatile(
        "mma.sync.aligned.m16n8k16.row.col.f32.bf16.bf16.f32 "
        "{%0,%1,%2,%3}, {%4,%5,%6,%7}, {%8,%9}, {%0,%1,%2,%3};\n"
        : "+f"(d[0]), "+f"(d[1]), "+f"(d[2]), "+f"(d[3])
        : "r"(a[0]), "r"(a[1]), "r"(a[2]), "r"(a[3]), "r"(b[0]), "r"(b[1]));
}
__device__ __forceinline__ void cp_async16(void* smem_dst, const void* gsrc, int src_bytes) {
    unsigned saddr = (unsigned)__cvta_generic_to_shared(smem_dst);
    asm volatile("cp.async.cg.shared.global [%0], [%1], 16, %2;\n"
                 :: "r"(saddr), "l"(gsrc), "r"(src_bytes));
}
__device__ __forceinline__ void cp_commit() {
    asm volatile("cp.async.commit_group;\n");
}
template <int N>
__device__ __forceinline__ void cp_wait() {
    asm volatile("cp.async.wait_group %0;\n" :: "n"(N));
}

// ---------------------------------------------------------------------------
// fp32 -> bf16 hi/lo split (grid-stride over float4)
// ---------------------------------------------------------------------------
__global__ void split_kernel(const float* __restrict__ src,
                             __nv_bfloat16* __restrict__ hi,
                             __nv_bfloat16* __restrict__ lo, int n4)
{
    int i = blockIdx.x * blockDim.x + threadIdx.x;
    if (i >= n4) return;
    float4 v = ((const float4*)src)[i];
    __nv_bfloat16 h0 = __float2bfloat16(v.x);
    __nv_bfloat16 h1 = __float2bfloat16(v.y);
    __nv_bfloat16 h2 = __float2bfloat16(v.z);
    __nv_bfloat16 h3 = __float2bfloat16(v.w);
    __nv_bfloat162* H = (__nv_bfloat162*)hi;
    __nv_bfloat162* L = (__nv_bfloat162*)lo;
    H[2 * i]     = __halves2bfloat162(h0, h1);
    H[2 * i + 1] = __halves2bfloat162(h2, h3);
    L[2 * i]     = __halves2bfloat162(
        __float2bfloat16(v.x - __bfloat162float(h0)),
        __float2bfloat16(v.y - __bfloat162float(h1)));
    L[2 * i + 1] = __halves2bfloat162(
        __float2bfloat16(v.z - __bfloat162float(h2)),
        __float2bfloat16(v.w - __bfloat162float(h3)));
}

// ---------------------------------------------------------------------------
// dtype detection
// ---------------------------------------------------------------------------
__global__ void detect_dtype_kernel(const int* __restrict__ ei, int e) {
    int nz = 0;
    int lim = e < 4096 ? e : 4096;
    for (int i = threadIdx.x; i < lim; i += blockDim.x) nz |= ei[2 * i + 1];
    int any = __syncthreads_or(nz);
    if (threadIdx.x == 0) g_is64 = (any == 0) ? 1 : 0;
}

// ---------------------------------------------------------------------------
// GEMM1 (tensor core, pre-split bf16, 2-stage cp.async pipeline)
// g_h = relu(x @ w1^T + b1); BM=128, BN=128, BK=32, 8 warps (4m x 2n).
// ---------------------------------------------------------------------------
#define ASTR 40                      // smem row stride (bf16)
#define TILE_E (128 * ASTR)          // per array per stage

__global__ __launch_bounds__(256) void gemm1_mma_kernel(
    const float* __restrict__ bias, int M)
{
    extern __shared__ __nv_bfloat16 sm[];
    __nv_bfloat16* Ah = sm;
    __nv_bfloat16* Al = sm + 2 * TILE_E;
    __nv_bfloat16* Bh = sm + 4 * TILE_E;
    __nv_bfloat16* Bl = sm + 6 * TILE_E;

    const int tid = threadIdx.x;
    const int bm = blockIdx.y * 128;
    const int bn = blockIdx.x * 128;

    const int wid    = tid >> 5;
    const int lane   = tid & 31;
    const int warp_m = wid & 3;
    const int warp_n = wid >> 2;
    const int g      = lane >> 2;
    const int tg     = lane & 3;

    auto prefetch = [&](int kt, int buf) {
        const int k0 = kt * 32;
#pragma unroll
        for (int it = 0; it < 2; it++) {
            int id  = tid + it * 256;     // 0..511 chunk ids
            int row = id >> 2;
            int c   = (id & 3) * 8;       // bf16 offset within 32-k tile
            int av  = (bm + row < M) ? 16 : 0;
            size_t asrc = (size_t)(bm + row) * KIN + k0 + c;
            cp_async16(&Ah[buf * TILE_E + row * ASTR + c], g_xhi + asrc, av);
            cp_async16(&Al[buf * TILE_E + row * ASTR + c], g_xlo + asrc, av);
            size_t bsrc = (size_t)(bn + row) * KIN + k0 + c;
            cp_async16(&Bh[buf * TILE_E + row * ASTR + c], g_w1hi + bsrc, 16);
            cp_async16(&Bl[buf * TILE_E + row * ASTR + c], g_w1lo + bsrc, 16);
        }
        cp_commit();
    };

    float acc[2][8][4];
#pragma unroll
    for (int i = 0; i < 2; i++)
#pragma unroll
        for (int j = 0; j < 8; j++)
#pragma unroll
            for (int q = 0; q < 4; q++) acc[i][j][q] = 0.0f;

    prefetch(0, 0);

    const int NT = KIN / 32;   // 16
    for (int kt = 0; kt < NT; kt++) {
        const int buf = kt & 1;
        if (kt + 1 < NT) { prefetch(kt + 1, buf ^ 1); cp_wait<1>(); }
        else             { cp_wait<0>(); }
        __syncthreads();

        const __nv_bfloat16* AhB = Ah + buf * TILE_E;
        const __nv_bfloat16* AlB = Al + buf * TILE_E;
        const __nv_bfloat16* BhB = Bh + buf * TILE_E;
        const __nv_bfloat16* BlB = Bl + buf * TILE_E;

#pragma unroll
        for (int s = 0; s < 2; s++) {
            const int ks = s * 16;
            unsigned aHi[2][4], aLo[2][4];
#pragma unroll
            for (int mi = 0; mi < 2; mi++) {
                int r0 = warp_m * 32 + mi * 16 + g;
                int kk = ks + tg * 2;
                aHi[mi][0] = *(const unsigned*)&AhB[r0 * ASTR + kk];
                aHi[mi][1] = *(const unsigned*)&AhB[(r0 + 8) * ASTR + kk];
                aHi[mi][2] = *(const unsigned*)&AhB[r0 * ASTR + kk + 8];
                aHi[mi][3] = *(const unsigned*)&AhB[(r0 + 8) * ASTR + kk + 8];
                aLo[mi][0] = *(const unsigned*)&AlB[r0 * ASTR + kk];
                aLo[mi][1] = *(const unsigned*)&AlB[(r0 + 8) * ASTR + kk];
                aLo[mi][2] = *(const unsigned*)&AlB[r0 * ASTR + kk + 8];
                aLo[mi][3] = *(const unsigned*)&AlB[(r0 + 8) * ASTR + kk + 8];
            }
            unsigned bHi[8][2], bLo[8][2];
#pragma unroll
            for (int ni = 0; ni < 8; ni++) {
                int nrow = warp_n * 64 + ni * 8 + g;
                int kk = ks + tg * 2;
                bHi[ni][0] = *(const unsigned*)&BhB[nrow * ASTR + kk];
                bHi[ni][1] = *(const unsigned*)&BhB[nrow * ASTR + kk + 8];
                bLo[ni][0] = *(const unsigned*)&BlB[nrow * ASTR + kk];
                bLo[ni][1] = *(const unsigned*)&BlB[nrow * ASTR + kk + 8];
            }
#pragma unroll
            for (int mi = 0; mi < 2; mi++)
#pragma unroll
                for (int ni = 0; ni < 8; ni++) {
                    mma_bf16(acc[mi][ni], aHi[mi], bHi[ni]);
                    mma_bf16(acc[mi][ni], aHi[mi], bLo[ni]);
                    mma_bf16(acc[mi][ni], aLo[mi], bHi[ni]);
                }
        }
        __syncthreads();
    }

    // epilogue: bias + relu -> g_h
#pragma unroll
    for (int mi = 0; mi < 2; mi++) {
#pragma unroll
        for (int ni = 0; ni < 8; ni++) {
            int row0 = bm + warp_m * 32 + mi * 16 + g;
            int col  = bn + warp_n * 64 + ni * 8 + tg * 2;
            float bx = bias[col], by = bias[col + 1];
            if (row0 < M) {
                float2 v = make_float2(fmaxf(acc[mi][ni][0] + bx, 0.f),
                                       fmaxf(acc[mi][ni][1] + by, 0.f));
                *(float2*)&g_h[(size_t)row0 * HID + col] = v;
            }
            if (row0 + 8 < M) {
                float2 v = make_float2(fmaxf(acc[mi][ni][2] + bx, 0.f),
                                       fmaxf(acc[mi][ni][3] + by, 0.f));
                *(float2*)&g_h[(size_t)(row0 + 8) * HID + col] = v;
            }
        }
    }
}

// ---------------------------------------------------------------------------
// Per-node 1/max(||f||, eps)
// ---------------------------------------------------------------------------
__global__ void inv_norm_kernel(const float* __restrict__ f, int n)
{
    const int warp = (blockIdx.x * blockDim.x + threadIdx.x) >> 5;
    if (warp >= n) return;
    const int lane = threadIdx.x & 31;
    const float4* F = (const float4*)(f ? f : (const float*)g_h);
    const size_t base = (size_t)warp * (HID / 4);
    float4 a = F[base + lane], b = F[base + 32 + lane];
    float s = dot8(a, b, a, b);
    s = warp_sum(s);
    if (lane == 0)
        g_inv[warp] = 1.0f / fmaxf(sqrtf(s), 1e-12f);
}

// ---------------------------------------------------------------------------
// CSR build
// ---------------------------------------------------------------------------
__global__ void zero_cnt_kernel(int n) {
    int i = blockIdx.x * blockDim.x + threadIdx.x;
    if (i < n) g_cnt[i] = 0;
}

__global__ void count_kernel(const int* __restrict__ ei, int e, int n) {
    int i = blockIdx.x * blockDim.x + threadIdx.x;
    if (i < e) {
        int d = clampN(edge_id(ei, e, 1, i, g_is64), n);
        atomicAdd(&g_cnt[d], 1);
    }
}

__global__ __launch_bounds__(1024) void scan_kernel(int n) {
    __shared__ int sums[1024];
    const int tid = threadIdx.x;
    const int CH = (n + 1023) / 1024;
    const int start = tid * CH;

    int s = 0;
    for (int i = 0; i < CH; i++) {
        int idx = start + i;
        if (idx < n) s += g_cnt[idx];
    }
    sums[tid] = s;
    __syncthreads();
#pragma unroll
    for (int off = 1; off < 1024; off <<= 1) {
        int v = (tid >= off) ? sums[tid - off] : 0;
        __syncthreads();
        sums[tid] += v;
        __syncthreads();
    }
    int run = (tid == 0) ? 0 : sums[tid - 1];
    for (int i = 0; i < CH; i++) {
        int idx = start + i;
        if (idx < n) {
            g_rowptr[idx] = run;
            g_cursor[idx] = run;
            run += g_cnt[idx];
        }
    }
    if (tid == 1023) g_rowptr[n] = sums[1023];
}

__global__ void scatter_kernel(const int* __restrict__ ei, int e, int n) {
    int i = blockIdx.x * blockDim.x + threadIdx.x;
    if (i < e) {
        const int is64 = g_is64;
        int d = clampN(edge_id(ei, e, 1, i, is64), n);
        int sidx = clampN(edge_id(ei, e, 0, i, is64), n);
        int p = atomicAdd(&g_cursor[d], 1);
        if (p < NEDGES) g_col[p] = sidx;
    }
}

// ---------------------------------------------------------------------------
// AGNN propagation — warp per node, online softmax, 2-way unrolled.
// ---------------------------------------------------------------------------
__global__ __launch_bounds__(256) void agnn_kernel(
    const float* __restrict__ f,
    const float* __restrict__ beta_ptr,
    float* __restrict__ out, int n)
{
    const int node = (blockIdx.x * blockDim.x + threadIdx.x) >> 5;
    if (node >= n) return;
    const int lane = threadIdx.x & 31;

    const float beta = beta_ptr ? __ldg(beta_ptr) : 1.0f;

    const float4* F = (const float4*)(f ? f : (const float*)g_h);
    const size_t base = (size_t)node * (HID / 4);

    float4 fi0 = F[base + lane];
    float4 fi1 = F[base + 32 + lane];
    const float invi = g_inv[node];

    float d = dot8(fi0, fi1, fi0, fi1);
    d = warp_sum(d);
    float m = beta * d * invi * invi;
    float s = 1.0f;
    float4 acc0 = fi0;
    float4 acc1 = fi1;

    const int beg = g_rowptr[node];
    const int end = g_rowptr[node + 1];
    int e = beg;

    for (; e + 1 < end; e += 2) {
        const int j0 = g_col[e];
        const int j1 = g_col[e + 1];
        const size_t jb0 = (size_t)j0 * (HID / 4);
        const size_t jb1 = (size_t)j1 * (HID / 4);
        float4 fa0 = F[jb0 + lane];
        float4 fa1 = F[jb0 + 32 + lane];
        float4 fb0 = F[jb1 + lane];
        float4 fb1 = F[jb1 + 32 + lane];

        float pa = dot8(fi0, fi1, fa0, fa1);
        float pb = dot8(fi0, fi1, fb0, fb1);
#pragma unroll
        for (int o = 16; o > 0; o >>= 1) {
            pa += __shfl_xor_sync(0xFFFFFFFFu, pa, o);
            pb += __shfl_xor_sync(0xFFFFFFFFu, pb, o);
        }
        const float sc_a = beta * pa * invi * g_inv[j0];
        const float sc_b = beta * pb * invi * g_inv[j1];

        {
            const float mn = fmaxf(m, sc_a);
            const float cs = __expf(m - mn);
            const float w  = __expf(sc_a - mn);
            s = s * cs + w;
            acc0.x = acc0.x * cs + w * fa0.x;  acc0.y = acc0.y * cs + w * fa0.y;
            acc0.z = acc0.z * cs + w * fa0.z;  acc0.w = acc0.w * cs + w * fa0.w;
            acc1.x = acc1.x * cs + w * fa1.x;  acc1.y = acc1.y * cs + w * fa1.y;
            acc1.z = acc1.z * cs + w * fa1.z;  acc1.w = acc1.w * cs + w * fa1.w;
            m = mn;
        }
        {
            const float mn = fmaxf(m, sc_b);
            const float cs = __expf(m - mn);
            const float w  = __expf(sc_b - mn);
            s = s * cs + w;
            acc0.x = acc0.x * cs + w * fb0.x;  acc0.y = acc0.y * cs + w * fb0.y;
            acc0.z = acc0.z * cs + w * fb0.z;  acc0.w = acc0.w * cs + w * fb0.w;
            acc1.x = acc1.x * cs + w * fb1.x;  acc1.y = acc1.y * cs + w * fb1.y;
            acc1.z = acc1.z * cs + w * fb1.z;  acc1.w = acc1.w * cs + w * fb1.w;
            m = mn;
        }
    }

    for (; e < end; e++) {
        const int j = g_col[e];
        const size_t jb = (size_t)j * (HID / 4);
        float4 fj0 = F[jb + lane];
        float4 fj1 = F[jb + 32 + lane];

        float pd = dot8(fi0, fi1, fj0, fj1);
        pd = warp_sum(pd);
        const float score = beta * pd * invi * g_inv[j];

        const float mn = fmaxf(m, score);
        const float cs = __expf(m - mn);
        const float w  = __expf(score - mn);
        s = s * cs + w;
        acc0.x = acc0.x * cs + w * fj0.x;  acc0.y = acc0.y * cs + w * fj0.y;
        acc0.z = acc0.z * cs + w * fj0.z;  acc0.w = acc0.w * cs + w * fj0.w;
        acc1.x = acc1.x * cs + w * fj1.x;  acc1.y = acc1.y * cs + w * fj1.y;
        acc1.z = acc1.z * cs + w * fj1.z;  acc1.w = acc1.w * cs + w * fj1.w;
        m = mn;
    }

    const float r = 1.0f / s;
    float4 o0 = make_float4(acc0.x * r, acc0.y * r, acc0.z * r, acc0.w * r);
    float4 o1 = make_float4(acc1.x * r, acc1.y * r, acc1.z * r, acc1.w * r);
    float4* O = (float4*)out;
    O[base + lane]      = o0;
    O[base + 32 + lane] = o1;
}

// ---------------------------------------------------------------------------
// GEMM2 tiled + log_softmax
// ---------------------------------------------------------------------------
__global__ __launch_bounds__(256) void gemm2_tile_kernel(
    const float* __restrict__ z,
    const float* __restrict__ w2,
    const float* __restrict__ b2,
    float* __restrict__ logits, int n)
{
    __shared__ float Zs[32][132];
    __shared__ float Ws[32][68];

    const int tid = threadIdx.x;
    const int bm = blockIdx.x * 128;
    const int tm = tid >> 4;
    const int tn = tid & 15;

    float acc[8][4];
#pragma unroll
    for (int i = 0; i < 8; i++)
#pragma unroll
        for (int j = 0; j < 4; j++) acc[i][j] = 0.0f;

    for (int k0 = 0; k0 < HID; k0 += 32) {
#pragma unroll
        for (int it = 0; it < 4; it++) {
            int id  = tid + it * 256;
            int row = id >> 3;
            int c4  = (id & 7) * 4;
            float4 v = make_float4(0.f, 0.f, 0.f, 0.f);
            if (bm + row < n)
                v = *(const float4*)&z[(size_t)(bm + row) * HID + k0 + c4];
            Zs[c4 + 0][row] = v.x; Zs[c4 + 1][row] = v.y;
            Zs[c4 + 2][row] = v.z; Zs[c4 + 3][row] = v.w;
        }
#pragma unroll
        for (int it = 0; it < 2; it++) {
            int id = tid + it * 256;
            int row = id >> 3;
            int c4  = (id & 7) * 4;
            float4 v = *(const float4*)&w2[(size_t)row * HID + k0 + c4];
            Ws[c4 + 0][row] = v.x; Ws[c4 + 1][row] = v.y;
            Ws[c4 + 2][row] = v.z; Ws[c4 + 3][row] = v.w;
        }
        __syncthreads();

#pragma unroll
        for (int kk = 0; kk < 32; kk++) {
            float4 ra0 = *(float4*)&Zs[kk][tm * 8];
            float4 ra1 = *(float4*)&Zs[kk][tm * 8 + 4];
            float4 rb  = *(float4*)&Ws[kk][tn * 4];
            float ra[8] = {ra0.x, ra0.y, ra0.z, ra0.w, ra1.x, ra1.y, ra1.z, ra1.w};
            float rbv[4] = {rb.x, rb.y, rb.z, rb.w};
#pragma unroll
            for (int i = 0; i < 8; i++)
#pragma unroll
                for (int j = 0; j < 4; j++)
                    acc[i][j] += ra[i] * rbv[j];
        }
        __syncthreads();
    }

#pragma unroll
    for (int i = 0; i < 8; i++) {
        int row = bm + tm * 8 + i;
        if (row >= n) continue;
#pragma unroll
        for (int j = 0; j < 4; j++)
            logits[(size_t)row * NOUT + tn * 4 + j] = acc[i][j] + b2[tn * 4 + j];
    }
}

__global__ void lsm_kernel(float* __restrict__ lp, int n)
{
    const int node = (blockIdx.x * blockDim.x + threadIdx.x) >> 5;
    if (node >= n) return;
    const int lane = threadIdx.x & 31;
    float2 v = *(float2*)&lp[(size_t)node * NOUT + lane * 2];
    float mx = warp_max(fmaxf(v.x, v.y));
    float se = warp_sum(__expf(v.x - mx) + __expf(v.y - mx));
    float lse = mx + logf(se);
    v.x -= lse; v.y -= lse;
    *(float2*)&lp[(size_t)node * NOUT + lane * 2] = v;
}

// ---------------------------------------------------------------------------
// Launch — gemm1 at launch index 4 (ncu capture slot)
// ---------------------------------------------------------------------------
extern "C" void kernel_launch(void* const* d_in, const int* in_sizes, int n_in,
                              void* d_out, int out_size)
{
    const float* x     = (const float*)d_in[0];
    const int*   ei    = (const int*)d_in[1];
    const float* w1    = (const float*)d_in[2];
    const float* b1    = (const float*)d_in[3];
    const float* beta2 = (const float*)d_in[4];
    const float* w2    = (const float*)d_in[5];
    const float* b2    = (const float*)d_in[6];

    const int N = in_sizes[0] / KIN;
    const int E = in_sizes[1] / 2;

    float* out = (float*)d_out;
    float* z1 = out;
    float* z2 = out + (size_t)N * HID;
    float* lp = out + (size_t)2 * N * HID;

    // raise dynamic smem limit for gemm1 (82 KB); immediate API, not captured
    cudaFuncSetAttribute(gemm1_mma_kernel,
                         cudaFuncAttributeMaxDynamicSharedMemorySize,
                         8 * TILE_E * (int)sizeof(__nv_bfloat16));

    __nv_bfloat16 *xhi, *xlo, *w1hi, *w1lo;
    cudaGetSymbolAddress((void**)&xhi,  g_xhi);
    cudaGetSymbolAddress((void**)&xlo,  g_xlo);
    cudaGetSymbolAddress((void**)&w1hi, g_w1hi);
    cudaGetSymbolAddress((void**)&w1lo, g_w1lo);

    // 1: dtype detect   2: split w1   3: split x   4: gemm1 (capture slot)
    detect_dtype_kernel<<<1, 256>>>(ei, E);
    split_kernel<<<(HID * KIN / 4 + 255) / 256, 256>>>(w1, w1hi, w1lo, HID * KIN / 4);
    {
        int n4 = (int)((size_t)N * KIN / 4);
        split_kernel<<<(n4 + 255) / 256, 256>>>(x, xhi, xlo, n4);
    }
    {
        dim3 grid(HID / 128, (N + 127) / 128);
        size_t smem = 8 * TILE_E * sizeof(__nv_bfloat16);
        gemm1_mma_kernel<<<grid, 256, smem>>>(b1, N);
    }

    // CSR build
    zero_cnt_kernel<<<(N + 255) / 256, 256>>>(N);
    count_kernel<<<(E + 255) / 256, 256>>>(ei, E, N);
    scan_kernel<<<1, 1024>>>(N);
    scatter_kernel<<<(E + 255) / 256, 256>>>(ei, E, N);

    const int gridN = (N + 7) / 8;

    inv_norm_kernel<<<gridN, 256>>>(nullptr, N);
    agnn_kernel<<<gridN, 256>>>(nullptr, nullptr, z1, N);

    inv_norm_kernel<<<gridN, 256>>>(z1, N);
    agnn_kernel<<<gridN, 256>>>(z1, beta2, z2, N);

    gemm2_tile_kernel<<<(N + 127) / 128, 256>>>(z2, w2, b2, lp, N);
    lsm_kernel<<<gridN, 256>>>(lp, N);
}